// round 1
// baseline (speedup 1.0000x reference)
#include <cuda_runtime.h>
#include <math.h>
#include <stdint.h>

// Problem constants
#define NB    16          // batch
#define CIN   256         // channels / cond dim
#define NSP   4096        // spatial 64*64
#define HID   128         // heads*dim_head
#define HEADS 4
#define DH    32
#define NSPLIT 16         // split-K for context

// ---------------- scratch (device globals; allocation-free) ----------------
__device__ float g_film[NB][512];                       // sk|shk|sv|shv
__device__ float g_q [NB][HID][NSP];                    // q (raw, then softmaxed*scale in place)
__device__ float g_ek[NB][HID][NSP];                    // exp(k_film)
__device__ float g_vn[NB][HID][NSP];                    // v_film / 4096
__device__ float g_sumexp[NB][HID];
__device__ float g_ctxp[NSPLIT][NB][HEADS][DH][DH];     // split-K partials (deterministic)
__device__ float g_M[NB][CIN][HID];                     // folded W_out @ blockdiag(C^T)

// ---------------- 1) FiLM params: cond -> silu -> W_cond + b_cond ----------
__global__ __launch_bounds__(256) void k_film(const float* __restrict__ cond,
                                              const float* __restrict__ Wc,
                                              const float* __restrict__ bc) {
    int b = blockIdx.x;
    __shared__ float sa[CIN];
    int t = threadIdx.x;
    float cv = cond[b * CIN + t];
    sa[t] = cv / (1.f + expf(-cv));   // silu
    __syncthreads();
    for (int o = t; o < 512; o += 256) {
        float s = bc[o];
        const float* w = Wc + (size_t)o * CIN;
        #pragma unroll 8
        for (int c = 0; c < CIN; ++c) s += w[c] * sa[c];
        g_film[b][o] = s;
    }
}

// ---------------- 2) qkv GEMM + FiLM + exp/scale epilogue -------------------
// C(384 x 4096) = W_qkv(384x256) @ x_b(256x4096); BM=128, BN=128, BK=16; 8x8/thread.
// blockIdx.y selects q/k/v row band (0/1/2) -> uniform epilogue branch.
__global__ __launch_bounds__(256) void k_qkv(const float* __restrict__ x,
                                             const float* __restrict__ Wqkv) {
    const int b  = blockIdx.z;
    const int kind = blockIdx.y;            // 0=q rows, 1=k rows, 2=v rows
    const int rb = kind * 128;
    const int nb = blockIdx.x * 128;
    __shared__ float As[16][128];
    __shared__ float Bs[16][128];
    const int t  = threadIdx.x;
    const int tx = t & 15, ty = t >> 4;
    const float* xb = x + (size_t)b * CIN * NSP;

    float acc[8][8];
    #pragma unroll
    for (int i = 0; i < 8; ++i)
        #pragma unroll
        for (int j = 0; j < 8; ++j) acc[i][j] = 0.f;

    for (int k0 = 0; k0 < CIN; k0 += 16) {
        #pragma unroll
        for (int i = 0; i < 8; ++i) {           // A: 128 rows x 16 k
            int lin = t + i * 256;
            int row = lin >> 4, kk = lin & 15;
            As[kk][row] = Wqkv[(size_t)(rb + row) * CIN + k0 + kk];
        }
        #pragma unroll
        for (int i = 0; i < 8; ++i) {           // B: 16 k x 128 n (coalesced)
            int lin = t + i * 256;
            int kk = lin >> 7, j = lin & 127;
            Bs[kk][j] = xb[(size_t)(k0 + kk) * NSP + nb + j];
        }
        __syncthreads();
        #pragma unroll
        for (int kk = 0; kk < 16; ++kk) {
            float a[8], bb[8];
            float4 a0 = *(const float4*)&As[kk][ty * 8];
            float4 a1 = *(const float4*)&As[kk][ty * 8 + 4];
            float4 b0 = *(const float4*)&Bs[kk][tx * 8];
            float4 b1 = *(const float4*)&Bs[kk][tx * 8 + 4];
            a[0]=a0.x;a[1]=a0.y;a[2]=a0.z;a[3]=a0.w;a[4]=a1.x;a[5]=a1.y;a[6]=a1.z;a[7]=a1.w;
            bb[0]=b0.x;bb[1]=b0.y;bb[2]=b0.z;bb[3]=b0.w;bb[4]=b1.x;bb[5]=b1.y;bb[6]=b1.z;bb[7]=b1.w;
            #pragma unroll
            for (int i = 0; i < 8; ++i)
                #pragma unroll
                for (int j = 0; j < 8; ++j) acc[i][j] += a[i] * bb[j];
        }
        __syncthreads();
    }

    // epilogue: q raw, k -> exp((1+sk)k+shk), v -> ((1+sv)v+shv)/4096
    #pragma unroll
    for (int i = 0; i < 8; ++i) {
        int c = ty * 8 + i;                     // channel in [0,128)
        float s0 = 1.f, s1 = 0.f;
        if (kind == 1) { s0 = 1.f + g_film[b][c];       s1 = g_film[b][128 + c]; }
        if (kind == 2) { s0 = 1.f + g_film[b][256 + c]; s1 = g_film[b][384 + c]; }
        #pragma unroll
        for (int j = 0; j < 8; ++j) {
            int n = nb + tx * 8 + j;
            float v = acc[i][j];
            if (kind == 0)      g_q [b][c][n] = v;
            else if (kind == 1) g_ek[b][c][n] = expf(fmaf(s0, v, s1));
            else                g_vn[b][c][n] = fmaf(s0, v, s1) * (1.f / 4096.f);
        }
    }
}

// ---------------- 3) q softmax over the 32 channels of each head ------------
__global__ __launch_bounds__(256) void k_qsm() {
    int t = blockIdx.x * 256 + threadIdx.x;   // < 16*4*4096
    int n = t & 4095;
    int h = (t >> 12) & 3;
    int b = t >> 14;
    float v[32], m = -1e30f;
    #pragma unroll
    for (int c = 0; c < 32; ++c) { v[c] = g_q[b][h * 32 + c][n]; m = fmaxf(m, v[c]); }
    float s = 0.f;
    #pragma unroll
    for (int c = 0; c < 32; ++c) { v[c] = expf(v[c] - m); s += v[c]; }
    float inv = 0.17677669529663687f / s;     // (1/sqrt(32)) / sum
    #pragma unroll
    for (int c = 0; c < 32; ++c) g_q[b][h * 32 + c][n] = v[c] * inv;
}

// ---------------- 4) row sums of exp(k) over n ------------------------------
__global__ __launch_bounds__(256) void k_sum() {
    int row = blockIdx.x;                     // 0..NB*HID-1
    int b = row >> 7, c = row & 127;
    const float* p = &g_ek[b][c][0];
    float s = 0.f;
    for (int i = threadIdx.x; i < NSP; i += 256) s += p[i];
    __shared__ float sb[256];
    sb[threadIdx.x] = s; __syncthreads();
    for (int st = 128; st > 0; st >>= 1) {
        if (threadIdx.x < st) sb[threadIdx.x] += sb[threadIdx.x + st];
        __syncthreads();
    }
    if (threadIdx.x == 0) g_sumexp[b][c] = sb[0];
}

// ---------------- 5) context split-K: C[c,e] partial = sum_n ek*vn ----------
__global__ __launch_bounds__(256) void k_ctx() {
    int bh = blockIdx.y; int b = bh >> 2, h = bh & 3;
    int sp = blockIdx.x;                       // split id
    int nbase0 = sp * (NSP / NSPLIT);          // 256 n per split
    __shared__ float eks[32][64];
    __shared__ float vns[32][65];              // padded: avoid e-stride conflicts
    int t = threadIdx.x;
    int e = t & 31, cbase = t >> 5;            // c = cbase + 8*i
    float acc[4] = {0.f, 0.f, 0.f, 0.f};
    for (int ch = 0; ch < 4; ++ch) {
        int nb2 = nbase0 + ch * 64;
        #pragma unroll
        for (int i = 0; i < 8; ++i) {
            int lin = t + i * 256; int r = lin >> 6, col = lin & 63;
            eks[r][col] = g_ek[b][h * 32 + r][nb2 + col];
            vns[r][col] = g_vn[b][h * 32 + r][nb2 + col];
        }
        __syncthreads();
        #pragma unroll 4
        for (int j = 0; j < 64; ++j) {
            float ve = vns[e][j];
            #pragma unroll
            for (int i = 0; i < 4; ++i) acc[i] += eks[cbase + 8 * i][j] * ve;
        }
        __syncthreads();
    }
    #pragma unroll
    for (int i = 0; i < 4; ++i) g_ctxp[sp][b][h][cbase + 8 * i][e] = acc[i];
}

// ---------------- 6) fold M_b = W_out @ blockdiag(C_h^T) --------------------
__global__ __launch_bounds__(256) void k_M(const float* __restrict__ Wout) {
    int b = blockIdx.x;
    __shared__ float Cs[HEADS][DH][DH];
    int t = threadIdx.x;
    for (int lin = t; lin < HEADS * DH * DH; lin += 256) {
        int h = lin >> 10, c = (lin >> 5) & 31, e2 = lin & 31;
        float s = 0.f;
        #pragma unroll
        for (int sp = 0; sp < NSPLIT; ++sp) s += g_ctxp[sp][b][h][c][e2];
        Cs[h][c][e2] = s / g_sumexp[b][h * 32 + c];
    }
    __syncthreads();
    int o = t;                                  // output channel 0..255
    for (int h = 0; h < HEADS; ++h) {
        float wo[32];
        #pragma unroll
        for (int e2 = 0; e2 < 32; ++e2) wo[e2] = Wout[(size_t)o * HID + h * 32 + e2];
        for (int c = 0; c < 32; ++c) {
            float s = 0.f;
            #pragma unroll
            for (int e2 = 0; e2 < 32; ++e2) s += wo[e2] * Cs[h][c][e2];
            g_M[b][o][h * 32 + c] = s;
        }
    }
}

// ---------------- 7) y = M_b @ q + b_out, fused channel LayerNorm -----------
// BM=256 (all channels in-block -> LN local), BN=32, BK chunks of 16.
__global__ __launch_bounds__(256) void k_out(const float* __restrict__ bout,
                                             const float* __restrict__ g,
                                             float* __restrict__ out) {
    int b  = blockIdx.y;
    int n0 = blockIdx.x * 32;
    __shared__ float sh[256 * 33 + 64];        // GEMM tiles / ys / stats (reused)
    float* Ms = sh;                            // [16][256]
    float* Bs = sh + 16 * 256;                 // [16][32]
    int t = threadIdx.x;

    float acc[32];
    #pragma unroll
    for (int j = 0; j < 32; ++j) acc[j] = 0.f;

    for (int k0 = 0; k0 < HID; k0 += 16) {
        #pragma unroll
        for (int i = 0; i < 16; ++i) {
            int lin = t + i * 256; int o = lin >> 4, kk = lin & 15;
            Ms[kk * 256 + o] = g_M[b][o][k0 + kk];
        }
        #pragma unroll
        for (int i = 0; i < 2; ++i) {
            int lin = t + i * 256; int kk = lin >> 5, j = lin & 31;
            Bs[kk * 32 + j] = g_q[b][k0 + kk][n0 + j];
        }
        __syncthreads();
        #pragma unroll
        for (int kk = 0; kk < 16; ++kk) {
            float a = Ms[kk * 256 + t];
            const float4* b4 = (const float4*)(Bs + kk * 32);
            #pragma unroll
            for (int j4 = 0; j4 < 8; ++j4) {
                float4 bb = b4[j4];
                acc[j4 * 4 + 0] += a * bb.x;
                acc[j4 * 4 + 1] += a * bb.y;
                acc[j4 * 4 + 2] += a * bb.z;
                acc[j4 * 4 + 3] += a * bb.w;
            }
        }
        __syncthreads();
    }

    // + bias, stash into padded ys[256][33]
    float bo = bout[t];
    float* ys = sh;
    #pragma unroll
    for (int j = 0; j < 32; ++j) ys[t * 33 + j] = acc[j] + bo;
    __syncthreads();

    // per-column mean/var over 256 channels: 8 threads per column
    int j = t >> 3, r0 = t & 7;
    float s1 = 0.f, s2 = 0.f;
    for (int r = r0; r < 256; r += 8) {
        float v = ys[r * 33 + j];
        s1 += v; s2 += v * v;
    }
    #pragma unroll
    for (int off = 4; off > 0; off >>= 1) {
        s1 += __shfl_down_sync(0xffffffffu, s1, off, 8);
        s2 += __shfl_down_sync(0xffffffffu, s2, off, 8);
    }
    float* stats = sh + 256 * 33;
    if (r0 == 0) {
        float mean = s1 * (1.f / 256.f);
        float var  = s2 * (1.f / 256.f) - mean * mean;
        stats[j]      = mean;
        stats[32 + j] = rsqrtf(var + 1e-5f);
    }
    __syncthreads();

    // coalesced store from smem
    #pragma unroll 4
    for (int i = 0; i < 32; ++i) {
        int row = i * 8 + (t >> 5);
        int col = t & 31;
        float v = (ys[row * 33 + col] - stats[col]) * stats[32 + col] * g[row];
        out[((size_t)b * CIN + row) * NSP + n0 + col] = v;
    }
}

// ---------------- launch ----------------------------------------------------
extern "C" void kernel_launch(void* const* d_in, const int* in_sizes, int n_in,
                              void* d_out, int out_size) {
    const float* x    = (const float*)d_in[0];
    const float* cond = (const float*)d_in[1];
    const float* Wqkv = (const float*)d_in[2];
    const float* Wc   = (const float*)d_in[3];
    const float* bc   = (const float*)d_in[4];
    const float* Wout = (const float*)d_in[5];
    const float* bout = (const float*)d_in[6];
    const float* g    = (const float*)d_in[7];
    float* out = (float*)d_out;

    k_film<<<NB, 256>>>(cond, Wc, bc);
    k_qkv <<<dim3(NSP / 128, 3, NB), 256>>>(x, Wqkv);
    k_qsm <<<(NB * HEADS * NSP) / 256, 256>>>();
    k_sum <<<NB * HID, 256>>>();
    k_ctx <<<dim3(NSPLIT, NB * HEADS), 256>>>();
    k_M   <<<NB, 256>>>(Wout);
    k_out <<<dim3(NSP / 32, NB), 256>>>(bout, g, out);
}

// round 12
// speedup vs baseline: 2.4703x; 2.4703x over previous
#include <cuda_runtime.h>
#include <math.h>
#include <stdint.h>

// Problem constants
#define NB    16          // batch
#define CIN   256         // channels / cond dim
#define NSP   4096        // spatial 64*64
#define HID   128         // heads*dim_head
#define HEADS 4
#define DH    32
#define NSPLIT 16         // split-K for context
#define NT128 32          // number of 128-wide n tiles

// ---------------- scratch (device globals; allocation-free) ----------------
__device__ float g_film[NB][512];                       // sk|shk|sv|shv
__device__ float g_q [NB][HID][NSP];                    // q raw
__device__ float g_ek[NB][HID][NSP];                    // exp(k_film)
__device__ float g_vn[NB][HID][NSP];                    // v_film / 4096
__device__ float g_spart[NT128][NB][HID];               // per-ntile partial sums of exp(k)
__device__ float g_ctxp[NSPLIT][NB][HEADS][DH][DH];     // split-K partials (deterministic)
__device__ float g_M[NB][CIN][HID];                     // folded W_out @ blockdiag(C^T)

// ---------------- tf32 helpers ---------------------------------------------
__device__ __forceinline__ float cvt_tf32(float x) {
    float y; asm("cvt.rna.tf32.f32 %0, %1;" : "=f"(y) : "f"(x)); return y;
}
__device__ __forceinline__ void cvt4(float4& v) {
    v.x = cvt_tf32(v.x); v.y = cvt_tf32(v.y); v.z = cvt_tf32(v.z); v.w = cvt_tf32(v.w);
}
__device__ __forceinline__ void mma8(float* d, const uint32_t* a, const uint32_t* b) {
    asm volatile("mma.sync.aligned.m16n8k8.row.col.f32.tf32.tf32.f32 "
                 "{%0,%1,%2,%3}, {%4,%5,%6,%7}, {%8,%9}, {%0,%1,%2,%3};"
                 : "+f"(d[0]), "+f"(d[1]), "+f"(d[2]), "+f"(d[3])
                 : "r"(a[0]), "r"(a[1]), "r"(a[2]), "r"(a[3]),
                   "r"(b[0]), "r"(b[1]));
}

// ---------------- 1) FiLM params: cond -> silu -> W_cond + b_cond ----------
__global__ __launch_bounds__(256) void k_film(const float* __restrict__ cond,
                                              const float* __restrict__ Wc,
                                              const float* __restrict__ bc) {
    int b = blockIdx.x;
    __shared__ float sa[CIN];
    int t = threadIdx.x;
    float cv = cond[b * CIN + t];
    sa[t] = cv / (1.f + expf(-cv));   // silu
    __syncthreads();
    for (int o = t; o < 512; o += 256) {
        float s = bc[o];
        const float* w = Wc + (size_t)o * CIN;
        #pragma unroll 8
        for (int c = 0; c < CIN; ++c) s += w[c] * sa[c];
        g_film[b][o] = s;
    }
}

// ---------------- 2) qkv GEMM (tf32 mma) + FiLM/exp epilogue ----------------
// C(384 x 4096) = W_qkv(384x256) @ x_b(256x4096); BM=128, BN=128, BK=32.
// 8 warps as 4(M) x 2(N); warp tile 32x64 via m16n8k8 (2x8 mma tiles).
__global__ __launch_bounds__(256, 2) void k_qkv(const float* __restrict__ x,
                                                const float* __restrict__ Wqkv) {
    const int b    = blockIdx.z;
    const int kind = blockIdx.y;            // 0=q, 1=k, 2=v
    const int rb   = kind * 128;
    const int nb   = blockIdx.x * 128;
    __shared__ float As[128][36];           // [m][k] padded -> conflict-free frag reads
    __shared__ float Bs[32][132];           // [k][n] padded
    __shared__ float ssum[128];
    const int t = threadIdx.x;
    const int warp = t >> 5, lane = t & 31;
    const int g = lane >> 2, tig = lane & 3;
    const int wm = warp >> 1, wn = warp & 1;
    const float* xb = x + (size_t)b * CIN * NSP;

    if (t < 128) ssum[t] = 0.f;

    float acc[2][8][4];
    #pragma unroll
    for (int i = 0; i < 2; ++i)
        #pragma unroll
        for (int j = 0; j < 8; ++j)
            #pragma unroll
            for (int r = 0; r < 4; ++r) acc[i][j][r] = 0.f;

    for (int k0 = 0; k0 < CIN; k0 += 32) {
        #pragma unroll
        for (int i = 0; i < 4; ++i) {       // A: 128 rows x 32 k
            int idx = t + i * 256;
            int row = idx >> 3, k4 = (idx & 7) * 4;
            float4 v = *(const float4*)&Wqkv[(size_t)(rb + row) * CIN + k0 + k4];
            cvt4(v);
            *(float4*)&As[row][k4] = v;
        }
        #pragma unroll
        for (int i = 0; i < 4; ++i) {       // B: 32 k x 128 n
            int idx = t + i * 256;
            int kk = idx >> 5, n4 = (idx & 31) * 4;
            float4 v = *(const float4*)&xb[(size_t)(k0 + kk) * NSP + nb + n4];
            cvt4(v);
            *(float4*)&Bs[kk][n4] = v;
        }
        __syncthreads();
        #pragma unroll
        for (int ks = 0; ks < 4; ++ks) {
            const int kk = ks * 8;
            uint32_t af[2][4], bf[8][2];
            #pragma unroll
            for (int mt = 0; mt < 2; ++mt) {
                int r = wm * 32 + mt * 16 + g;
                af[mt][0] = __float_as_uint(As[r    ][kk + tig]);
                af[mt][1] = __float_as_uint(As[r + 8][kk + tig]);
                af[mt][2] = __float_as_uint(As[r    ][kk + tig + 4]);
                af[mt][3] = __float_as_uint(As[r + 8][kk + tig + 4]);
            }
            #pragma unroll
            for (int nt = 0; nt < 8; ++nt) {
                int n = wn * 64 + nt * 8 + g;
                bf[nt][0] = __float_as_uint(Bs[kk + tig    ][n]);
                bf[nt][1] = __float_as_uint(Bs[kk + tig + 4][n]);
            }
            #pragma unroll
            for (int mt = 0; mt < 2; ++mt)
                #pragma unroll
                for (int nt = 0; nt < 8; ++nt)
                    mma8(acc[mt][nt], af[mt], bf[nt]);
        }
        __syncthreads();
    }

    // epilogue: q raw; k -> exp(film); v -> film/4096 (+ k row-sum partials)
    float rowsum[2][2] = {{0.f, 0.f}, {0.f, 0.f}};
    #pragma unroll
    for (int mt = 0; mt < 2; ++mt) {
        const int c0 = wm * 32 + mt * 16 + g;
        const int c1 = c0 + 8;
        float s0a = 1.f, s1a = 0.f, s0b = 1.f, s1b = 0.f;
        if (kind == 1) {
            s0a = 1.f + g_film[b][c0]; s1a = g_film[b][128 + c0];
            s0b = 1.f + g_film[b][c1]; s1b = g_film[b][128 + c1];
        } else if (kind == 2) {
            s0a = 1.f + g_film[b][256 + c0]; s1a = g_film[b][384 + c0];
            s0b = 1.f + g_film[b][256 + c1]; s1b = g_film[b][384 + c1];
        }
        #pragma unroll
        for (int nt = 0; nt < 8; ++nt) {
            const int n = nb + wn * 64 + nt * 8 + tig * 2;
            float d0 = acc[mt][nt][0], d1 = acc[mt][nt][1];
            float d2 = acc[mt][nt][2], d3 = acc[mt][nt][3];
            if (kind == 0) {
                *(float2*)&g_q[b][c0][n] = make_float2(d0, d1);
                *(float2*)&g_q[b][c1][n] = make_float2(d2, d3);
            } else if (kind == 1) {
                float e0 = expf(fmaf(s0a, d0, s1a));
                float e1 = expf(fmaf(s0a, d1, s1a));
                float e2 = expf(fmaf(s0b, d2, s1b));
                float e3 = expf(fmaf(s0b, d3, s1b));
                *(float2*)&g_ek[b][c0][n] = make_float2(e0, e1);
                *(float2*)&g_ek[b][c1][n] = make_float2(e2, e3);
                rowsum[mt][0] += e0 + e1;
                rowsum[mt][1] += e2 + e3;
            } else {
                const float inv = 1.f / 4096.f;
                *(float2*)&g_vn[b][c0][n] =
                    make_float2(fmaf(s0a, d0, s1a) * inv, fmaf(s0a, d1, s1a) * inv);
                *(float2*)&g_vn[b][c1][n] =
                    make_float2(fmaf(s0b, d2, s1b) * inv, fmaf(s0b, d3, s1b) * inv);
            }
        }
    }
    if (kind == 1) {
        #pragma unroll
        for (int mt = 0; mt < 2; ++mt)
            #pragma unroll
            for (int r = 0; r < 2; ++r) {
                float s = rowsum[mt][r];
                s += __shfl_xor_sync(0xffffffffu, s, 1);
                s += __shfl_xor_sync(0xffffffffu, s, 2);
                if (tig == 0)  // exactly 2 adds per channel (wn=0,1) -> commutative, deterministic
                    atomicAdd(&ssum[wm * 32 + mt * 16 + g + r * 8], s);
            }
        __syncthreads();
        if (t < 128) g_spart[blockIdx.x][b][t] = ssum[t];
    }
}

// ---------------- 3) context split-K: C[c,e] partial = sum_n ek*vn ----------
__global__ __launch_bounds__(256) void k_ctx() {
    int bh = blockIdx.y; int b = bh >> 2, h = bh & 3;
    int sp = blockIdx.x;                       // split id
    int nbase0 = sp * (NSP / NSPLIT);          // 256 n per split
    __shared__ float eks[32][64];
    __shared__ float vns[32][65];              // padded: avoid e-stride conflicts
    int t = threadIdx.x;
    int e = t & 31, cbase = t >> 5;            // c = cbase + 8*i
    float acc[4] = {0.f, 0.f, 0.f, 0.f};
    for (int ch = 0; ch < 4; ++ch) {
        int nb2 = nbase0 + ch * 64;
        #pragma unroll
        for (int i = 0; i < 8; ++i) {
            int lin = t + i * 256; int r = lin >> 6, col = lin & 63;
            eks[r][col] = g_ek[b][h * 32 + r][nb2 + col];
            vns[r][col] = g_vn[b][h * 32 + r][nb2 + col];
        }
        __syncthreads();
        #pragma unroll 4
        for (int j = 0; j < 64; ++j) {
            float ve = vns[e][j];
            #pragma unroll
            for (int i = 0; i < 4; ++i) acc[i] += eks[cbase + 8 * i][j] * ve;
        }
        __syncthreads();
    }
    #pragma unroll
    for (int i = 0; i < 4; ++i) g_ctxp[sp][b][h][cbase + 8 * i][e] = acc[i];
}

// ---------------- 4) fold M_b = W_out @ blockdiag(C_h^T) --------------------
// Also reduces the per-tile exp(k) row-sum partials (was a separate kernel).
__global__ __launch_bounds__(256) void k_M(const float* __restrict__ Wout) {
    int b = blockIdx.x;
    __shared__ float Cs[HEADS][DH][DH];
    __shared__ float se[HID];
    int t = threadIdx.x;
    if (t < HID) {                              // reduce sum of exp(k) partials
        float s = 0.f;
        #pragma unroll
        for (int sp = 0; sp < NT128; ++sp) s += g_spart[sp][b][t];
        se[t] = s;
    }
    __syncthreads();
    for (int lin = t; lin < HEADS * DH * DH; lin += 256) {
        int h = lin >> 10, c = (lin >> 5) & 31, e2 = lin & 31;
        float s = 0.f;
        #pragma unroll
        for (int sp = 0; sp < NSPLIT; ++sp) s += g_ctxp[sp][b][h][c][e2];
        Cs[h][c][e2] = s / se[h * 32 + c];
    }
    __syncthreads();
    int o = t;                                  // output channel 0..255
    for (int h = 0; h < HEADS; ++h) {
        float wo[32];
        #pragma unroll
        for (int e2 = 0; e2 < 32; ++e2) wo[e2] = Wout[(size_t)o * HID + h * 32 + e2];
        for (int c = 0; c < 32; ++c) {
            float s = 0.f;
            #pragma unroll
            for (int e2 = 0; e2 < 32; ++e2) s += wo[e2] * Cs[h][c][e2];
            g_M[b][o][h * 32 + c] = s;
        }
    }
}

// ---------------- 5) y = M_b @ softmax_q + b_out (tf32 mma), fused LN -------
// BM=256 (all channels in-block), BN=32, K=128. 8 warps, warp tile 32x32.
// Smem budget: As[256][32] (xor-swizzled) + Bs[128][32] (xor-swizzled)
//            = 12288 floats = 49152 B = exactly the 48 KB static limit.
// LN phase reuses the same buffer as ys[256][33] (+stat in the tail).
#define ASW(row, k)  ((row) * 32 + (((k) ^ (((row) & 7) << 2)) & 31))
#define BSW(kk, n)   ((kk) * 32 + (((n) ^ (((kk) & 7) << 2)) & 31))
__global__ __launch_bounds__(256) void k_out(const float* __restrict__ bout,
                                             const float* __restrict__ gw,
                                             float* __restrict__ out) {
    const int b  = blockIdx.y;
    const int n0 = blockIdx.x * 32;
    __shared__ float sh[256 * 32 + 128 * 32];   // 49152 B total
    float* As = sh;                  // [256][32] xor-swizzled; later ys[256][33]
    float* Bs = sh + 256 * 32;       // [128][32] xor-swizzled q tile
    const int t = threadIdx.x;
    const int warp = t >> 5, lane = t & 31;
    const int g = lane >> 2, tig = lane & 3;
    const int m0 = warp * 32;

    // ---- load full raw q tile [128 k][32 n] (xor-swizzled stores) ----
    // float4 at n4 (mult of 4): xor by (kk&7)*4 is a multiple of 4 -> alignment ok
    #pragma unroll
    for (int i = 0; i < 4; ++i) {
        int idx = t + i * 256;
        int kk = idx >> 3, n4 = (idx & 7) * 4;
        float4 v = *(const float4*)&g_q[b][kk][n0 + n4];
        *(float4*)&Bs[BSW(kk, n4)] = v;
    }
    __syncthreads();

    // ---- head softmax over channels, per column; write back as tf32 ----
    // t<128: head h=t>>5, column n=t&31. Address (32c + n^(4(c&7))): for fixed
    // lane set over n=0..31, banks are a permutation -> conflict-free.
    if (t < 128) {
        int h = t >> 5, n = t & 31;
        float v[32], m = -1e30f;
        #pragma unroll
        for (int c = 0; c < 32; ++c) { v[c] = Bs[BSW(h * 32 + c, n)]; m = fmaxf(m, v[c]); }
        float s = 0.f;
        #pragma unroll
        for (int c = 0; c < 32; ++c) { v[c] = expf(v[c] - m); s += v[c]; }
        float inv = 0.17677669529663687f / s;   // (1/sqrt(32)) / sum
        #pragma unroll
        for (int c = 0; c < 32; ++c) Bs[BSW(h * 32 + c, n)] = cvt_tf32(v[c] * inv);
    }

    float acc[2][4][4];
    #pragma unroll
    for (int i = 0; i < 2; ++i)
        #pragma unroll
        for (int j = 0; j < 4; ++j)
            #pragma unroll
            for (int r = 0; r < 4; ++r) acc[i][j][r] = 0.f;

    for (int k0 = 0; k0 < HID; k0 += 32) {
        #pragma unroll
        for (int i = 0; i < 8; ++i) {      // A: 256 rows x 32 k (xor-swizzled)
            int idx = t + i * 256;
            int row = idx >> 3, k4 = (idx & 7) * 4;
            float4 v = *(const float4*)&g_M[b][row][k0 + k4];
            cvt4(v);
            *(float4*)&As[ASW(row, k4)] = v;
        }
        __syncthreads();
        #pragma unroll
        for (int ks = 0; ks < 4; ++ks) {
            const int kk = ks * 8;
            uint32_t af[2][4], bf[4][2];
            // A frag: fixed k, rows r and r+8 -> same (r&7) -> same xor; reads at
            // 8 distinct rows g per quad -> banks (k^4(g&7)) all distinct. OK.
            #pragma unroll
            for (int mt = 0; mt < 2; ++mt) {
                int r = m0 + mt * 16 + g;
                af[mt][0] = __float_as_uint(As[ASW(r,     kk + tig)]);
                af[mt][1] = __float_as_uint(As[ASW(r + 8, kk + tig)]);
                af[mt][2] = __float_as_uint(As[ASW(r,     kk + tig + 4)]);
                af[mt][3] = __float_as_uint(As[ASW(r + 8, kk + tig + 4)]);
            }
            #pragma unroll
            for (int nt = 0; nt < 4; ++nt) {
                int n = nt * 8 + g;
                bf[nt][0] = __float_as_uint(Bs[BSW(k0 + kk + tig,     n)]);
                bf[nt][1] = __float_as_uint(Bs[BSW(k0 + kk + tig + 4, n)]);
            }
            #pragma unroll
            for (int mt = 0; mt < 2; ++mt)
                #pragma unroll
                for (int nt = 0; nt < 4; ++nt)
                    mma8(acc[mt][nt], af[mt], bf[nt]);
        }
        __syncthreads();
    }

    // stash y (+bias) into padded ys[256][33] (reuses sh; GEMM done)
    float* ys = sh;                    // 256*33 = 8448 floats < 12288
    float* stat = sh + 256 * 33;       // 64 floats, still within buffer
    #pragma unroll
    for (int mt = 0; mt < 2; ++mt) {
        const int r0 = m0 + mt * 16 + g, r1 = r0 + 8;
        const float b0v = bout[r0], b1v = bout[r1];
        #pragma unroll
        for (int nt = 0; nt < 4; ++nt) {
            const int n = nt * 8 + tig * 2;
            ys[r0 * 33 + n    ] = acc[mt][nt][0] + b0v;
            ys[r0 * 33 + n + 1] = acc[mt][nt][1] + b0v;
            ys[r1 * 33 + n    ] = acc[mt][nt][2] + b1v;
            ys[r1 * 33 + n + 1] = acc[mt][nt][3] + b1v;
        }
    }
    __syncthreads();

    // per-column mean/var over 256 channels: 8 threads per column
    int j = t >> 3, r0_ = t & 7;
    float s1 = 0.f, s2 = 0.f;
    for (int r = r0_; r < 256; r += 8) {
        float v = ys[r * 33 + j];
        s1 += v; s2 += v * v;
    }
    #pragma unroll
    for (int off = 4; off > 0; off >>= 1) {
        s1 += __shfl_down_sync(0xffffffffu, s1, off, 8);
        s2 += __shfl_down_sync(0xffffffffu, s2, off, 8);
    }
    if (r0_ == 0) {
        float mean = s1 * (1.f / 256.f);
        float var  = s2 * (1.f / 256.f) - mean * mean;
        stat[j]      = mean;
        stat[32 + j] = rsqrtf(var + 1e-5f);
    }
    __syncthreads();

    // coalesced store from smem
    #pragma unroll 4
    for (int i = 0; i < 32; ++i) {
        int row = i * 8 + (t >> 5);
        int col = t & 31;
        float v = (ys[row * 33 + col] - stat[col]) * stat[32 + col] * gw[row];
        out[((size_t)b * CIN + row) * NSP + n0 + col] = v;
    }
}

// ---------------- launch ----------------------------------------------------
extern "C" void kernel_launch(void* const* d_in, const int* in_sizes, int n_in,
                              void* d_out, int out_size) {
    const float* x    = (const float*)d_in[0];
    const float* cond = (const float*)d_in[1];
    const float* Wqkv = (const float*)d_in[2];
    const float* Wc   = (const float*)d_in[3];
    const float* bc   = (const float*)d_in[4];
    const float* Wout = (const float*)d_in[5];
    const float* bout = (const float*)d_in[6];
    const float* g    = (const float*)d_in[7];
    float* out = (float*)d_out;

    k_film<<<NB, 256>>>(cond, Wc, bc);
    k_qkv <<<dim3(NT128, 3, NB), 256>>>(x, Wqkv);
    k_ctx <<<dim3(NSPLIT, NB * HEADS), 256>>>();
    k_M   <<<NB, 256>>>(Wout);
    k_out <<<dim3(NSP / 32, NB), 256>>>(bout, g, out);
}